// round 15
// baseline (speedup 1.0000x reference)
#include <cuda_runtime.h>
#include <cuda_fp16.h>
#include <cstdint>

// Mosaic GEMM via fp16 HMMA: 2 CTAs/SM x 8 warps (32x32 warp tiles),
// 4-stage TK=64 cp.async pipeline, 1 sync/chunk, parts preloaded to smem,
// fast fp32->fp16 convert prologue (STG.128).
//   out[256,8192] = x @ W + bias,  W[k,n] = blocks[parts[k/64,n/64]][k%64][n%64]

#define KDIM 8192
#define NDIM 8192
#define BROWS 256
#define TM 64
#define TN 128
#define TK 64
#define NCHUNK 128          // KDIM / TK
#define THREADS 256

#define A_STRIDE_B 144      // 64 halves + 8 pad   (144 % 128 == 16 -> conflict-free)
#define B_STRIDE_B 272      // 128 halves + 8 pad  (272 % 128 == 16 -> conflict-free)
#define A_BYTES (TM * A_STRIDE_B)          // 9216
#define B_BYTES (TK * B_STRIDE_B)          // 17408
#define STAGE_BYTES (A_BYTES + B_BYTES)    // 26624
#define NSTAGE 4
#define PARTS_OFF (NSTAGE * STAGE_BYTES)   // 106496
#define SMEM_DYN (PARTS_OFF + NCHUNK * 8)  // +1024 = 107520/CTA; x2 = 215040

static __device__ __half g_xh[BROWS * KDIM];        // fp16 x
static __device__ __half g_wh[1024 * 64 * 64];      // fp16 blocks (native [p][k][n])

// ---------------- helpers ----------------
__device__ __forceinline__ uint32_t smem_u32(const void* p) {
    uint32_t a;
    asm("{ .reg .u64 t; cvta.to.shared.u64 t, %1; cvt.u32.u64 %0, t; }" : "=r"(a) : "l"(p));
    return a;
}
__device__ __forceinline__ uint32_t h2_bits(__half2 h) {
    return *reinterpret_cast<uint32_t*>(&h);
}
__device__ __forceinline__ void cp16(uint32_t dst, const __half* src) {
    asm volatile("cp.async.cg.shared.global [%0], [%1], 16;"
                 :: "r"(dst), "l"(__cvta_generic_to_global(src)));
}
__device__ __forceinline__ void ldsm4(uint32_t* r, uint32_t addr) {
    asm volatile("ldmatrix.sync.aligned.m8n8.x4.shared.b16 {%0,%1,%2,%3}, [%4];"
        : "=r"(r[0]), "=r"(r[1]), "=r"(r[2]), "=r"(r[3]) : "r"(addr));
}
__device__ __forceinline__ void ldsm4t(uint32_t* r, uint32_t addr) {
    asm volatile("ldmatrix.sync.aligned.m8n8.x4.trans.shared.b16 {%0,%1,%2,%3}, [%4];"
        : "=r"(r[0]), "=r"(r[1]), "=r"(r[2]), "=r"(r[3]) : "r"(addr));
}
__device__ __forceinline__ void mma16816(float* c, const uint32_t* a,
                                         uint32_t b0, uint32_t b1) {
    asm volatile(
        "mma.sync.aligned.m16n8k16.row.col.f32.f16.f16.f32 "
        "{%0,%1,%2,%3}, {%4,%5,%6,%7}, {%8,%9}, {%0,%1,%2,%3};"
        : "+f"(c[0]), "+f"(c[1]), "+f"(c[2]), "+f"(c[3])
        : "r"(a[0]), "r"(a[1]), "r"(a[2]), "r"(a[3]), "r"(b0), "r"(b1));
}

// ---------------- fused conversion kernel (8 floats/thread, STG.128) ----------------
// grid: [0,1024) -> x (2M floats), [1024,3072) -> blocks (4M floats)
__global__ void convert_all_kernel(const float* __restrict__ x,
                                   const float* __restrict__ blocks) {
    const int b = blockIdx.x;
    const float* src;
    __half* dst;
    size_t i;
    if (b < 1024) {
        i = ((size_t)b * 256 + threadIdx.x) * 8;
        src = x; dst = g_xh;
    } else {
        i = ((size_t)(b - 1024) * 256 + threadIdx.x) * 8;
        src = blocks; dst = g_wh;
    }
    const float4 v0 = *reinterpret_cast<const float4*>(src + i);
    const float4 v1 = *reinterpret_cast<const float4*>(src + i + 4);
    uint4 o;
    o.x = h2_bits(__floats2half2_rn(v0.x, v0.y));
    o.y = h2_bits(__floats2half2_rn(v0.z, v0.w));
    o.z = h2_bits(__floats2half2_rn(v1.x, v1.y));
    o.w = h2_bits(__floats2half2_rn(v1.z, v1.w));
    *reinterpret_cast<uint4*>(dst + i) = o;
}

// ---------------- main kernel ----------------
__global__ void __launch_bounds__(THREADS, 2)
mosaic_hmma_kernel(const int* __restrict__ parts,
                   const float* __restrict__ bias,
                   float* __restrict__ out)
{
    extern __shared__ __align__(128) char smem[];
    const uint32_t sb = smem_u32(smem);
    int2* sParts = reinterpret_cast<int2*>(smem + PARTS_OFF);
    const int tid  = threadIdx.x;
    const int wid  = tid >> 5;
    const int lane = tid & 31;
    const int m0 = blockIdx.y * TM;
    const int n0 = blockIdx.x * TN;
    const int o0 = blockIdx.x * 2;

    // preload all 128 part-pairs for this N column pair (o0 even -> 8B aligned)
    if (tid < NCHUNK)
        sParts[tid] = *reinterpret_cast<const int2*>(parts + tid * 128 + o0);
    __syncthreads();

    const int wm = (wid & 1) * 32;      // 2 warp-rows
    const int wn = (wid >> 1) * 32;     // 4 warp-cols (warp tile 32x32)
    const int lrow = lane & 15;
    const int lcol = (lane >> 4) * 8;

    float acc[2][4][4];
    #pragma unroll
    for (int a = 0; a < 2; ++a)
        #pragma unroll
        for (int b = 0; b < 4; ++b)
            #pragma unroll
            for (int c = 0; c < 4; ++c) acc[a][b][c] = 0.f;

    // cp.async mappings (256 threads, TK=64)
    const int ar = tid >> 3, ac = tid & 7;    // A: rows ar, ar+32 ; col-16B ac
    const int br = tid >> 4, bc = tid & 15;   // B: rows br+16*it (4 it); col-16B bc

    auto issue = [&](int i) {
        if (i < NCHUNK) {
            const int s = i & (NSTAGE - 1);
            const uint32_t abase = sb + s * STAGE_BYTES;
            const uint32_t bbase = abase + A_BYTES;
            const int2 pp = sParts[i];
            const size_t k0 = (size_t)i * TK;
            const __half* asrc = g_xh + (size_t)(m0 + ar) * KDIM + k0 + ac * 8;
            cp16(abase + ar * A_STRIDE_B + ac * 16, asrc);
            cp16(abase + (ar + 32) * A_STRIDE_B + ac * 16, asrc + (size_t)32 * KDIM);
            const __half* bsrc = g_wh + ((size_t)((bc < 8) ? pp.x : pp.y) << 12)
                               + br * 64 + (bc & 7) * 8;
            #pragma unroll
            for (int it = 0; it < 4; ++it)
                cp16(bbase + (br + it * 16) * B_STRIDE_B + bc * 16,
                     bsrc + it * 16 * 64);
        }
        asm volatile("cp.async.commit_group;" ::: "memory");
    };

    issue(0); issue(1); issue(2);

    for (int i = 0; i < NCHUNK; ++i) {
        asm volatile("cp.async.wait_group 2;" ::: "memory");
        __syncthreads();
        issue(i + 3);

        const uint32_t abase = sb + (i & (NSTAGE - 1)) * STAGE_BYTES;
        const uint32_t bbase = abase + A_BYTES;
        const uint32_t a_ad = abase + (wm + lrow) * A_STRIDE_B + lcol * 2;
        const uint32_t b_ad = bbase + lrow * B_STRIDE_B + (wn + lcol) * 2;

        #pragma unroll
        for (int kk = 0; kk < 4; ++kk) {               // four k16 steps
            uint32_t af[2][4];
            ldsm4(af[0], a_ad + kk * 32);
            ldsm4(af[1], a_ad + 16 * A_STRIDE_B + kk * 32);
            uint32_t bf[2][4];
            #pragma unroll
            for (int nt = 0; nt < 2; ++nt)
                ldsm4t(bf[nt], b_ad + kk * 16 * B_STRIDE_B + nt * 32);
            #pragma unroll
            for (int mt = 0; mt < 2; ++mt)
                #pragma unroll
                for (int nt = 0; nt < 2; ++nt) {
                    mma16816(acc[mt][nt * 2 + 0], af[mt], bf[nt][0], bf[nt][1]);
                    mma16816(acc[mt][nt * 2 + 1], af[mt], bf[nt][2], bf[nt][3]);
                }
        }
    }

    // -------- epilogue: bias + store --------
    const int qr = lane >> 2;
    const int qc = (lane & 3) * 2;
    #pragma unroll
    for (int mt = 0; mt < 2; ++mt) {
        const size_t r0 = (size_t)(m0 + wm + mt * 16 + qr);
        #pragma unroll
        for (int nj = 0; nj < 4; ++nj) {
            const int col = n0 + wn + nj * 8 + qc;
            const float2 bv = *reinterpret_cast<const float2*>(bias + col);
            float2 lo, hi;
            lo.x = acc[mt][nj][0] + bv.x;  lo.y = acc[mt][nj][1] + bv.y;
            hi.x = acc[mt][nj][2] + bv.x;  hi.y = acc[mt][nj][3] + bv.y;
            *reinterpret_cast<float2*>(out + r0 * NDIM + col)       = lo;
            *reinterpret_cast<float2*>(out + (r0 + 8) * NDIM + col) = hi;
        }
    }
}

// ---------------- launch ----------------
extern "C" void kernel_launch(void* const* d_in, const int* in_sizes, int n_in,
                              void* d_out, int out_size) {
    const float* x      = (const float*)d_in[0];   // [256, 8192]
    const float* blocks = (const float*)d_in[1];   // [1024, 64, 64]
    const float* bias   = (const float*)d_in[2];   // [8192]
    const int*   parts  = (const int*)d_in[3];     // [128, 128]
    float* out = (float*)d_out;                    // [256, 8192]

    convert_all_kernel<<<3072, 256>>>(x, blocks);

    cudaFuncSetAttribute(mosaic_hmma_kernel,
                         cudaFuncAttributeMaxDynamicSharedMemorySize, SMEM_DYN);
    dim3 grid(NDIM / TN, BROWS / TM);   // (64, 4) = 256 CTAs -> 2 per SM
    mosaic_hmma_kernel<<<grid, THREADS, SMEM_DYN>>>(parts, bias, out);
}

// round 16
// speedup vs baseline: 1.1082x; 1.1082x over previous
#include <cuda_runtime.h>
#include <cuda_fp16.h>
#include <cstdint>

// Mosaic GEMM via fp16 HMMA: 2 CTAs/SM x 8 warps (32x32 warp tiles),
// 4-stage TK=64 cp.async pipeline, 1 sync/chunk  (round-11 champion mainloop)
// + fast fp32->fp16 convert prologue (STG.128).
//   out[256,8192] = x @ W + bias,  W[k,n] = blocks[parts[k/64,n/64]][k%64][n%64]

#define KDIM 8192
#define NDIM 8192
#define BROWS 256
#define TM 64
#define TN 128
#define TK 64
#define NCHUNK 128          // KDIM / TK
#define THREADS 256

#define A_STRIDE_B 144      // 64 halves + 8 pad   (144 % 128 == 16 -> conflict-free)
#define B_STRIDE_B 272      // 128 halves + 8 pad  (272 % 128 == 16 -> conflict-free)
#define A_BYTES (TM * A_STRIDE_B)          // 9216
#define B_BYTES (TK * B_STRIDE_B)          // 17408
#define STAGE_BYTES (A_BYTES + B_BYTES)    // 26624
#define NSTAGE 4
#define SMEM_DYN (NSTAGE * STAGE_BYTES)    // 106496/CTA; 2 CTAs/SM = 212992

static __device__ __half g_xh[BROWS * KDIM];        // fp16 x
static __device__ __half g_wh[1024 * 64 * 64];      // fp16 blocks (native [p][k][n])

// ---------------- helpers ----------------
__device__ __forceinline__ uint32_t smem_u32(const void* p) {
    uint32_t a;
    asm("{ .reg .u64 t; cvta.to.shared.u64 t, %1; cvt.u32.u64 %0, t; }" : "=r"(a) : "l"(p));
    return a;
}
__device__ __forceinline__ uint32_t h2_bits(__half2 h) {
    return *reinterpret_cast<uint32_t*>(&h);
}
__device__ __forceinline__ void cp16(uint32_t dst, const __half* src) {
    asm volatile("cp.async.cg.shared.global [%0], [%1], 16;"
                 :: "r"(dst), "l"(__cvta_generic_to_global(src)));
}
__device__ __forceinline__ void ldsm4(uint32_t* r, uint32_t addr) {
    asm volatile("ldmatrix.sync.aligned.m8n8.x4.shared.b16 {%0,%1,%2,%3}, [%4];"
        : "=r"(r[0]), "=r"(r[1]), "=r"(r[2]), "=r"(r[3]) : "r"(addr));
}
__device__ __forceinline__ void ldsm4t(uint32_t* r, uint32_t addr) {
    asm volatile("ldmatrix.sync.aligned.m8n8.x4.trans.shared.b16 {%0,%1,%2,%3}, [%4];"
        : "=r"(r[0]), "=r"(r[1]), "=r"(r[2]), "=r"(r[3]) : "r"(addr));
}
__device__ __forceinline__ void mma16816(float* c, const uint32_t* a,
                                         uint32_t b0, uint32_t b1) {
    asm volatile(
        "mma.sync.aligned.m16n8k16.row.col.f32.f16.f16.f32 "
        "{%0,%1,%2,%3}, {%4,%5,%6,%7}, {%8,%9}, {%0,%1,%2,%3};"
        : "+f"(c[0]), "+f"(c[1]), "+f"(c[2]), "+f"(c[3])
        : "r"(a[0]), "r"(a[1]), "r"(a[2]), "r"(a[3]), "r"(b0), "r"(b1));
}

// ---------------- fused conversion kernel (8 floats/thread, STG.128) ----------------
// grid: [0,1024) -> x (2M floats), [1024,3072) -> blocks (4M floats)
__global__ void convert_all_kernel(const float* __restrict__ x,
                                   const float* __restrict__ blocks) {
    const int b = blockIdx.x;
    const float* src;
    __half* dst;
    size_t i;
    if (b < 1024) {
        i = ((size_t)b * 256 + threadIdx.x) * 8;
        src = x; dst = g_xh;
    } else {
        i = ((size_t)(b - 1024) * 256 + threadIdx.x) * 8;
        src = blocks; dst = g_wh;
    }
    const float4 v0 = *reinterpret_cast<const float4*>(src + i);
    const float4 v1 = *reinterpret_cast<const float4*>(src + i + 4);
    uint4 o;
    o.x = h2_bits(__floats2half2_rn(v0.x, v0.y));
    o.y = h2_bits(__floats2half2_rn(v0.z, v0.w));
    o.z = h2_bits(__floats2half2_rn(v1.x, v1.y));
    o.w = h2_bits(__floats2half2_rn(v1.z, v1.w));
    *reinterpret_cast<uint4*>(dst + i) = o;
}

// ---------------- main kernel (round-11 champion, unmodified) ----------------
__global__ void __launch_bounds__(THREADS, 2)
mosaic_hmma_kernel(const int* __restrict__ parts,
                   const float* __restrict__ bias,
                   float* __restrict__ out)
{
    extern __shared__ __align__(128) char smem[];
    const uint32_t sb = smem_u32(smem);
    const int tid  = threadIdx.x;
    const int wid  = tid >> 5;
    const int lane = tid & 31;
    const int m0 = blockIdx.y * TM;
    const int n0 = blockIdx.x * TN;
    const int o0 = blockIdx.x * 2;

    const int wm = (wid & 1) * 32;      // 2 warp-rows
    const int wn = (wid >> 1) * 32;     // 4 warp-cols (warp tile 32x32)
    const int lrow = lane & 15;
    const int lcol = (lane >> 4) * 8;

    float acc[2][4][4];
    #pragma unroll
    for (int a = 0; a < 2; ++a)
        #pragma unroll
        for (int b = 0; b < 4; ++b)
            #pragma unroll
            for (int c = 0; c < 4; ++c) acc[a][b][c] = 0.f;

    // cp.async mappings (256 threads, TK=64)
    const int ar = tid >> 3, ac = tid & 7;    // A: rows ar, ar+32 ; col-16B ac
    const int br = tid >> 4, bc = tid & 15;   // B: rows br+16*it (4 it); col-16B bc

    auto issue = [&](int i) {
        if (i < NCHUNK) {
            const int s = i & (NSTAGE - 1);
            const uint32_t abase = sb + s * STAGE_BYTES;
            const uint32_t bbase = abase + A_BYTES;
            const int p0 = parts[i * 128 + o0];
            const int p1 = parts[i * 128 + o0 + 1];
            const size_t k0 = (size_t)i * TK;
            const __half* asrc = g_xh + (size_t)(m0 + ar) * KDIM + k0 + ac * 8;
            cp16(abase + ar * A_STRIDE_B + ac * 16, asrc);
            cp16(abase + (ar + 32) * A_STRIDE_B + ac * 16, asrc + (size_t)32 * KDIM);
            const __half* bsrc = g_wh + ((size_t)((bc < 8) ? p0 : p1) << 12)
                               + br * 64 + (bc & 7) * 8;
            #pragma unroll
            for (int it = 0; it < 4; ++it)
                cp16(bbase + (br + it * 16) * B_STRIDE_B + bc * 16,
                     bsrc + it * 16 * 64);
        }
        asm volatile("cp.async.commit_group;" ::: "memory");
    };

    issue(0); issue(1); issue(2);

    for (int i = 0; i < NCHUNK; ++i) {
        asm volatile("cp.async.wait_group 2;" ::: "memory");
        __syncthreads();
        issue(i + 3);

        const uint32_t abase = sb + (i & (NSTAGE - 1)) * STAGE_BYTES;
        const uint32_t bbase = abase + A_BYTES;
        const uint32_t a_ad = abase + (wm + lrow) * A_STRIDE_B + lcol * 2;
        const uint32_t b_ad = bbase + lrow * B_STRIDE_B + (wn + lcol) * 2;

        #pragma unroll
        for (int kk = 0; kk < 4; ++kk) {               // four k16 steps
            uint32_t af[2][4];
            ldsm4(af[0], a_ad + kk * 32);
            ldsm4(af[1], a_ad + 16 * A_STRIDE_B + kk * 32);
            uint32_t bf[2][4];
            #pragma unroll
            for (int nt = 0; nt < 2; ++nt)
                ldsm4t(bf[nt], b_ad + kk * 16 * B_STRIDE_B + nt * 32);
            #pragma unroll
            for (int mt = 0; mt < 2; ++mt)
                #pragma unroll
                for (int nt = 0; nt < 2; ++nt) {
                    mma16816(acc[mt][nt * 2 + 0], af[mt], bf[nt][0], bf[nt][1]);
                    mma16816(acc[mt][nt * 2 + 1], af[mt], bf[nt][2], bf[nt][3]);
                }
        }
    }

    // -------- epilogue: bias + store --------
    const int qr = lane >> 2;
    const int qc = (lane & 3) * 2;
    #pragma unroll
    for (int mt = 0; mt < 2; ++mt) {
        const size_t r0 = (size_t)(m0 + wm + mt * 16 + qr);
        #pragma unroll
        for (int nj = 0; nj < 4; ++nj) {
            const int col = n0 + wn + nj * 8 + qc;
            const float2 bv = *reinterpret_cast<const float2*>(bias + col);
            float2 lo, hi;
            lo.x = acc[mt][nj][0] + bv.x;  lo.y = acc[mt][nj][1] + bv.y;
            hi.x = acc[mt][nj][2] + bv.x;  hi.y = acc[mt][nj][3] + bv.y;
            *reinterpret_cast<float2*>(out + r0 * NDIM + col)       = lo;
            *reinterpret_cast<float2*>(out + (r0 + 8) * NDIM + col) = hi;
        }
    }
}

// ---------------- launch ----------------
extern "C" void kernel_launch(void* const* d_in, const int* in_sizes, int n_in,
                              void* d_out, int out_size) {
    const float* x      = (const float*)d_in[0];   // [256, 8192]
    const float* blocks = (const float*)d_in[1];   // [1024, 64, 64]
    const float* bias   = (const float*)d_in[2];   // [8192]
    const int*   parts  = (const int*)d_in[3];     // [128, 128]
    float* out = (float*)d_out;                    // [256, 8192]

    convert_all_kernel<<<3072, 256>>>(x, blocks);

    cudaFuncSetAttribute(mosaic_hmma_kernel,
                         cudaFuncAttributeMaxDynamicSharedMemorySize, SMEM_DYN);
    dim3 grid(NDIM / TN, BROWS / TM);   // (64, 4) = 256 CTAs -> 2 per SM
    mosaic_hmma_kernel<<<grid, THREADS, SMEM_DYN>>>(parts, bias, out);
}

// round 17
// speedup vs baseline: 1.5289x; 1.3796x over previous
#include <cuda_runtime.h>
#include <cuda_fp16.h>
#include <cstdint>

// Mosaic GEMM via fp16 HMMA: 2 CTAs/SM, each CTA split into TWO independent
// 4-warp groups (named barriers) with private A copy + own B half + own
// 3-stage cp.async pipeline -> 4 desynced domains/SM without B-reuse loss.
//   out[256,8192] = x @ W + bias,  W[k,n] = blocks[parts[k/64,n/64]][k%64][n%64]

#define KDIM 8192
#define NDIM 8192
#define BROWS 256
#define TM 64
#define TN 128            // per CTA; 64 per group
#define TK 64
#define NCHUNK 128        // KDIM / TK
#define THREADS 256

#define STRIDE_B 144      // 64 halves + 8 pad (144 % 128 == 16 -> ldsm conflict-free)
#define GA_BYTES (64 * STRIDE_B)            // 9216  (A tile per group)
#define GB_BYTES (64 * STRIDE_B)            // 9216  (B half per group)
#define GSTAGE (GA_BYTES + GB_BYTES)        // 18432
#define NSTAGE 3
#define GROUP_BYTES (NSTAGE * GSTAGE)       // 55296 per group
#define SMEM_DYN (2 * GROUP_BYTES)          // 110592/CTA; 2 CTAs/SM = 221184

static __device__ __half g_xh[BROWS * KDIM];        // fp16 x
static __device__ __half g_wh[1024 * 64 * 64];      // fp16 blocks (native [p][k][n])

// ---------------- helpers ----------------
__device__ __forceinline__ uint32_t smem_u32(const void* p) {
    uint32_t a;
    asm("{ .reg .u64 t; cvta.to.shared.u64 t, %1; cvt.u32.u64 %0, t; }" : "=r"(a) : "l"(p));
    return a;
}
__device__ __forceinline__ uint32_t h2_bits(__half2 h) {
    return *reinterpret_cast<uint32_t*>(&h);
}
__device__ __forceinline__ void cp16(uint32_t dst, const __half* src) {
    asm volatile("cp.async.cg.shared.global [%0], [%1], 16;"
                 :: "r"(dst), "l"(__cvta_generic_to_global(src)));
}
__device__ __forceinline__ void ldsm4(uint32_t* r, uint32_t addr) {
    asm volatile("ldmatrix.sync.aligned.m8n8.x4.shared.b16 {%0,%1,%2,%3}, [%4];"
        : "=r"(r[0]), "=r"(r[1]), "=r"(r[2]), "=r"(r[3]) : "r"(addr));
}
__device__ __forceinline__ void ldsm4t(uint32_t* r, uint32_t addr) {
    asm volatile("ldmatrix.sync.aligned.m8n8.x4.trans.shared.b16 {%0,%1,%2,%3}, [%4];"
        : "=r"(r[0]), "=r"(r[1]), "=r"(r[2]), "=r"(r[3]) : "r"(addr));
}
__device__ __forceinline__ void mma16816(float* c, const uint32_t* a,
                                         uint32_t b0, uint32_t b1) {
    asm volatile(
        "mma.sync.aligned.m16n8k16.row.col.f32.f16.f16.f32 "
        "{%0,%1,%2,%3}, {%4,%5,%6,%7}, {%8,%9}, {%0,%1,%2,%3};"
        : "+f"(c[0]), "+f"(c[1]), "+f"(c[2]), "+f"(c[3])
        : "r"(a[0]), "r"(a[1]), "r"(a[2]), "r"(a[3]), "r"(b0), "r"(b1));
}
__device__ __forceinline__ void group_bar(int id) {
    asm volatile("bar.sync %0, 128;" :: "r"(id) : "memory");
}

// ---------------- fused conversion kernel (8 floats/thread, STG.128) ----------------
__global__ void convert_all_kernel(const float* __restrict__ x,
                                   const float* __restrict__ blocks) {
    const int b = blockIdx.x;
    const float* src;
    __half* dst;
    size_t i;
    if (b < 1024) {
        i = ((size_t)b * 256 + threadIdx.x) * 8;
        src = x; dst = g_xh;
    } else {
        i = ((size_t)(b - 1024) * 256 + threadIdx.x) * 8;
        src = blocks; dst = g_wh;
    }
    const float4 v0 = *reinterpret_cast<const float4*>(src + i);
    const float4 v1 = *reinterpret_cast<const float4*>(src + i + 4);
    uint4 o;
    o.x = h2_bits(__floats2half2_rn(v0.x, v0.y));
    o.y = h2_bits(__floats2half2_rn(v0.z, v0.w));
    o.z = h2_bits(__floats2half2_rn(v1.x, v1.y));
    o.w = h2_bits(__floats2half2_rn(v1.z, v1.w));
    *reinterpret_cast<uint4*>(dst + i) = o;
}

// ---------------- main kernel ----------------
__global__ void __launch_bounds__(THREADS, 2)
mosaic_hmma_kernel(const int* __restrict__ parts,
                   const float* __restrict__ bias,
                   float* __restrict__ out)
{
    extern __shared__ __align__(128) char smem[];
    const int tid  = threadIdx.x;
    const int gid  = tid >> 7;          // group 0: warps 0-3, group 1: warps 4-7
    const int gtid = tid & 127;
    const int gwid = gtid >> 5;
    const int lane = tid & 31;
    const uint32_t gbase = smem_u32(smem) + gid * GROUP_BYTES;
    const int m0 = blockIdx.y * TM;
    const int n0 = blockIdx.x * TN + gid * 64;
    const int oc = blockIdx.x * 2 + gid;   // this group's part column

    const int wm = (gwid & 1) * 32;     // 2 warp-rows
    const int wn = (gwid >> 1) * 32;    // 2 warp-cols within the group's 64
    const int lrow = lane & 15;
    const int lcol = (lane >> 4) * 8;
    const int barid = 1 + gid;

    float acc[2][4][4];
    #pragma unroll
    for (int a = 0; a < 2; ++a)
        #pragma unroll
        for (int b = 0; b < 4; ++b)
            #pragma unroll
            for (int c = 0; c < 4; ++c) acc[a][b][c] = 0.f;

    // cp.async mapping (128 threads/group): 64 rows x 8 x 16B per tile
    const int tr = gtid >> 3, tc = gtid & 7;   // rows tr+16*it (it<4), col-16B tc

    auto issue = [&](int i) {
        if (i < NCHUNK) {
            const uint32_t abase = gbase + (i % NSTAGE) * GSTAGE;
            const uint32_t bbase = abase + GA_BYTES;
            const int p = parts[i * 128 + oc];
            const size_t k0 = (size_t)i * TK;
            const __half* asrc = g_xh + (size_t)(m0 + tr) * KDIM + k0 + tc * 8;
            const __half* bsrc = g_wh + ((size_t)p << 12) + tr * 64 + tc * 8;
            #pragma unroll
            for (int it = 0; it < 4; ++it) {
                cp16(abase + (tr + it * 16) * STRIDE_B + tc * 16,
                     asrc + (size_t)it * 16 * KDIM);
                cp16(bbase + (tr + it * 16) * STRIDE_B + tc * 16,
                     bsrc + it * 16 * 64);
            }
        }
        asm volatile("cp.async.commit_group;" ::: "memory");
    };

    issue(0); issue(1);

    for (int i = 0; i < NCHUNK; ++i) {
        asm volatile("cp.async.wait_group 1;" ::: "memory");
        group_bar(barid);
        issue(i + 2);

        const uint32_t abase = gbase + (i % NSTAGE) * GSTAGE;
        const uint32_t bbase = abase + GA_BYTES;
        const uint32_t a_ad = abase + (wm + lrow) * STRIDE_B + lcol * 2;
        const uint32_t b_ad = bbase + lrow * STRIDE_B + (wn + lcol) * 2;

        #pragma unroll
        for (int kk = 0; kk < 4; ++kk) {               // four k16 steps
            uint32_t af[2][4];
            ldsm4(af[0], a_ad + kk * 32);
            ldsm4(af[1], a_ad + 16 * STRIDE_B + kk * 32);
            uint32_t bf[2][4];
            #pragma unroll
            for (int nt = 0; nt < 2; ++nt)
                ldsm4t(bf[nt], b_ad + kk * 16 * STRIDE_B + nt * 32);
            #pragma unroll
            for (int mt = 0; mt < 2; ++mt)
                #pragma unroll
                for (int nt = 0; nt < 2; ++nt) {
                    mma16816(acc[mt][nt * 2 + 0], af[mt], bf[nt][0], bf[nt][1]);
                    mma16816(acc[mt][nt * 2 + 1], af[mt], bf[nt][2], bf[nt][3]);
                }
        }
    }

    // -------- epilogue: bias + store --------
    const int qr = lane >> 2;
    const int qc = (lane & 3) * 2;
    #pragma unroll
    for (int mt = 0; mt < 2; ++mt) {
        const size_t r0 = (size_t)(m0 + wm + mt * 16 + qr);
        #pragma unroll
        for (int nj = 0; nj < 4; ++nj) {
            const int col = n0 + wn + nj * 8 + qc;
            const float2 bv = *reinterpret_cast<const float2*>(bias + col);
            float2 lo, hi;
            lo.x = acc[mt][nj][0] + bv.x;  lo.y = acc[mt][nj][1] + bv.y;
            hi.x = acc[mt][nj][2] + bv.x;  hi.y = acc[mt][nj][3] + bv.y;
            *reinterpret_cast<float2*>(out + r0 * NDIM + col)       = lo;
            *reinterpret_cast<float2*>(out + (r0 + 8) * NDIM + col) = hi;
        }
    }
}

// ---------------- launch ----------------
extern "C" void kernel_launch(void* const* d_in, const int* in_sizes, int n_in,
                              void* d_out, int out_size) {
    const float* x      = (const float*)d_in[0];   // [256, 8192]
    const float* blocks = (const float*)d_in[1];   // [1024, 64, 64]
    const float* bias   = (const float*)d_in[2];   // [8192]
    const int*   parts  = (const int*)d_in[3];     // [128, 128]
    float* out = (float*)d_out;                    // [256, 8192]

    convert_all_kernel<<<3072, 256>>>(x, blocks);

    cudaFuncSetAttribute(mosaic_hmma_kernel,
                         cudaFuncAttributeMaxDynamicSharedMemorySize, SMEM_DYN);
    dim3 grid(NDIM / TN, BROWS / TM);   // (64, 4) = 256 CTAs -> 2 per SM
    mosaic_hmma_kernel<<<grid, THREADS, SMEM_DYN>>>(parts, bias, out);
}